// round 10
// baseline (speedup 1.0000x reference)
#include <cuda_runtime.h>
#include <cuda_fp16.h>
#include <cstdint>

#define BB   32
#define CC   128
#define HH   56
#define WW   56
#define OUTC 256
#define KK   4
#define HIDN 64
#define HW   (HH*WW)

#define NK      36              // K chunks (1152 / 32)
#define NSTAGE  8
#define PREF    6               // chunks in flight
#define SLABR   58
#define SLAB    (SLABR*WW)      // 3248 halves
#define AS_B    80              // A smem row stride bytes (32 halves + 8 pad)
#define BS_B    464             // B smem row stride bytes (224 halves + 8 pad)
#define A_STAGE (128*AS_B)      // 10240
#define B_STAGE (32*BS_B)       // 14848
#define STAGE   (A_STAGE + B_STAGE)     // 25088
#define SMEM_TOTAL (NSTAGE*STAGE)       // 200704

// scratch
__device__ float  g_pooled[BB*CC];
__device__ float  g_attn[BB*KK];
__device__ __half g_wh[(size_t)BB*OUTC*1152];      // [b][o][ij*128+c]
__device__ __half g_xs[(size_t)3*BB*CC*SLAB];      // [dj+1][b][c][58][56], zero-padded rows

// ---------------------------------------------------------------- helpers
__device__ __forceinline__ uint32_t smem_u32(const void* p) {
    uint32_t a;
    asm("{ .reg .u64 t; cvta.to.shared.u64 t, %1; cvt.u32.u64 %0, t; }" : "=r"(a) : "l"(p));
    return a;
}
__device__ __forceinline__ void ldsm_x4(uint32_t& r0, uint32_t& r1, uint32_t& r2, uint32_t& r3,
                                        uint32_t addr) {
    asm volatile("ldmatrix.sync.aligned.m8n8.x4.shared.b16 {%0,%1,%2,%3}, [%4];"
                 : "=r"(r0), "=r"(r1), "=r"(r2), "=r"(r3) : "r"(addr));
}
__device__ __forceinline__ void ldsm_x4t(uint32_t& r0, uint32_t& r1, uint32_t& r2, uint32_t& r3,
                                         uint32_t addr) {
    asm volatile("ldmatrix.sync.aligned.m8n8.x4.trans.shared.b16 {%0,%1,%2,%3}, [%4];"
                 : "=r"(r0), "=r"(r1), "=r"(r2), "=r"(r3) : "r"(addr));
}
__device__ __forceinline__ void ldsm_x2t(uint32_t& r0, uint32_t& r1, uint32_t addr) {
    asm volatile("ldmatrix.sync.aligned.m8n8.x2.trans.shared.b16 {%0,%1}, [%2];"
                 : "=r"(r0), "=r"(r1) : "r"(addr));
}
// f16-accumulate HMMA: d = a*b + 0  (zero-start, resets chunk accumulator)
__device__ __forceinline__ void mma16816h_z(uint32_t* d, const uint32_t* a, const uint32_t* b,
                                            uint32_t z) {
    asm volatile("mma.sync.aligned.m16n8k16.row.col.f16.f16.f16.f16 "
                 "{%0,%1}, {%2,%3,%4,%5}, {%6,%7}, {%8,%9};"
                 : "=r"(d[0]), "=r"(d[1])
                 : "r"(a[0]), "r"(a[1]), "r"(a[2]), "r"(a[3]), "r"(b[0]), "r"(b[1]),
                   "r"(z), "r"(z));
}
// f16-accumulate HMMA: d += a*b
__device__ __forceinline__ void mma16816h(uint32_t* d, const uint32_t* a, const uint32_t* b) {
    asm volatile("mma.sync.aligned.m16n8k16.row.col.f16.f16.f16.f16 "
                 "{%0,%1}, {%2,%3,%4,%5}, {%6,%7}, {%0,%1};"
                 : "+r"(d[0]), "+r"(d[1])
                 : "r"(a[0]), "r"(a[1]), "r"(a[2]), "r"(a[3]), "r"(b[0]), "r"(b[1]));
}
__device__ __forceinline__ void cp16(uint32_t dst, const void* src) {
    asm volatile("cp.async.cg.shared.global [%0], [%1], 16;" :: "r"(dst), "l"(src));
}
#define CP_COMMIT() asm volatile("cp.async.commit_group;" ::: "memory")
#define CP_WAIT4()  asm volatile("cp.async.wait_group 4;" ::: "memory")
#define CP_WAIT0()  asm volatile("cp.async.wait_group 0;" ::: "memory")

// ---------------------------------------------------------------- x prep: fp16 shifts + pool
__global__ void xprep_kernel(const float* __restrict__ x) {
    int bc = blockIdx.x;
    const float* xp = x + (size_t)bc * HW;
    __half* d0 = g_xs + ((size_t)0*BB*CC + bc)*SLAB;
    __half* d1 = g_xs + ((size_t)1*BB*CC + bc)*SLAB;
    __half* d2 = g_xs + ((size_t)2*BB*CC + bc)*SLAB;
    int tid = threadIdx.x;
    if (tid < 56) {
        __half2 z = __floats2half2_rn(0.f, 0.f);
        *(__half2*)(d0 + tid*2) = z;  *(__half2*)(d0 + 57*WW + tid*2) = z;
        *(__half2*)(d1 + tid*2) = z;  *(__half2*)(d1 + 57*WW + tid*2) = z;
        *(__half2*)(d2 + tid*2) = z;  *(__half2*)(d2 + 57*WW + tid*2) = z;
    }
    float s = 0.f;
    #pragma unroll
    for (int it = 0; it < 7; it++) {
        int ip = tid + it*256;
        if (ip < HW/2) {
            int idx = ip*2;
            int w = idx % 56;
            float v0 = xp[idx], v1 = xp[idx+1];
            s += v0 + v1;
            float vm = (w > 0)  ? xp[idx-1] : 0.f;
            float vp = (w < 54) ? xp[idx+2] : 0.f;
            *(__half2*)(d0 + WW + idx) = __floats2half2_rn(vm, v0);
            *(__half2*)(d1 + WW + idx) = __floats2half2_rn(v0, v1);
            *(__half2*)(d2 + WW + idx) = __floats2half2_rn(v1, vp);
        }
    }
    #pragma unroll
    for (int o = 16; o; o >>= 1) s += __shfl_down_sync(0xffffffff, s, o);
    __shared__ float ws[8];
    int lane = tid & 31, wid = tid >> 5;
    if (lane == 0) ws[wid] = s;
    __syncthreads();
    if (tid == 0) {
        float t = 0.f;
        #pragma unroll
        for (int i = 0; i < 8; i++) t += ws[i];
        g_pooled[bc] = t * (1.0f / (float)HW);
    }
}

// ---------------------------------------------------------------- attn
__global__ void attn_kernel(const float* __restrict__ fc1_w, const float* __restrict__ fc1_b,
                            const float* __restrict__ fc2_w, const float* __restrict__ fc2_b) {
    int b = blockIdx.x;
    __shared__ float sp[CC];
    __shared__ float hdn[HIDN];
    int t = threadIdx.x;
    for (int i = t; i < CC; i += HIDN) sp[i] = g_pooled[b*CC + i];
    __syncthreads();
    float a = fc1_b[t];
    #pragma unroll 8
    for (int c = 0; c < CC; c++) a += sp[c] * fc1_w[t*CC + c];
    hdn[t] = fmaxf(a, 0.f);
    __syncthreads();
    if (t == 0) {
        float lg[KK];
        float mx = -1e30f;
        #pragma unroll
        for (int k = 0; k < KK; k++) {
            float s = fc2_b[k];
            for (int h = 0; h < HIDN; h++) s += hdn[h] * fc2_w[k*HIDN + h];
            lg[k] = s; mx = fmaxf(mx, s);
        }
        float den = 0.f;
        #pragma unroll
        for (int k = 0; k < KK; k++) { lg[k] = expf(lg[k] - mx); den += lg[k]; }
        float inv = 1.0f / den;
        #pragma unroll
        for (int k = 0; k < KK; k++) g_attn[b*KK + k] = lg[k] * inv;
    }
}

// ---------------------------------------------------------------- weight synthesis (fp16 out)
__global__ void synth_kernel(const float* __restrict__ bank) {
    __shared__ float sat[BB*KK];
    if (threadIdx.x < BB*KK) sat[threadIdx.x] = g_attn[threadIdx.x];
    __syncthreads();
    int idx = blockIdx.x * blockDim.x + threadIdx.x;
    int c   = idx & 127;
    int oij = idx >> 7;
    int ij  = oij % 9;
    int o   = oij / 9;
    float bv[KK];
    #pragma unroll
    for (int k = 0; k < KK; k++)
        bv[k] = __ldg(&bank[((size_t)k*OUTC + o) * 1152 + c*9 + ij]);
    size_t dst = (size_t)o*1152 + ij*128 + c;
    #pragma unroll 4
    for (int b = 0; b < BB; b++) {
        float w = 0.f;
        #pragma unroll
        for (int k = 0; k < KK; k++) w += sat[b*KK + k] * bv[k];
        g_wh[(size_t)b * (OUTC*1152) + dst] = __float2half_rn(w);
    }
}

// ---------------------------------------------------------------- fp16 mma.sync conv
// CTA: b=z, bm=y (128 o), nt=x (224 pos = 4 rows). 8 warps (2m x 4n), warp M64xN56.
// f16-accum HMMA per K=32 chunk, promoted to fp32 each chunk. 8-stage ring.
__global__ void __launch_bounds__(256, 1)
conv_mma_kernel(float* __restrict__ out) {
    extern __shared__ __align__(16) char smem[];

    int tid  = threadIdx.x;
    int wid  = tid >> 5;
    int lane = tid & 31;
    int wm   = wid >> 2;          // 0..1 -> m base wm*64
    int wn   = wid & 3;           // 0..3 -> n base wn*56
    int b    = blockIdx.z;
    int bm   = blockIdx.y;
    int nt   = blockIdx.x;        // 0..13
    int r0   = nt * 4;

    uint32_t sbase = smem_u32(smem);

    const __half* wg = g_wh + ((size_t)b * OUTC + bm*128) * 1152;

    float acc[4][7][4];
    #pragma unroll
    for (int i = 0; i < 4; i++)
        #pragma unroll
        for (int j = 0; j < 7; j++)
            #pragma unroll
            for (int q = 0; q < 4; q++) acc[i][j][q] = 0.f;

    // ---- A loader: 2 cp16/thread. row = tid>>2 (+64), q = tid&3.
    int ar = tid >> 2, aq = tid & 3;
    const __half* asrc = wg + (size_t)ar*1152 + aq*8;    // + ck*32 per chunk
    uint32_t dA = (uint32_t)ar*AS_B + aq*16;
    // ---- B loader: 3.5 cp16/thread. idx = tid + it*256; c = idx/28, q = idx%28.
    size_t   bso[4];
    uint32_t bdo[4];
    #pragma unroll
    for (int it = 0; it < 4; it++) {
        int idx = tid + it*256;
        int c   = idx / 28, q = idx - c*28;
        bso[it] = (size_t)c*SLAB + q*8;
        bdo[it] = (uint32_t)c*BS_B + q*16;
    }
    bool bhas3 = tid < 128;

    auto issue_chunk = [&](int ck) {
        uint32_t ab = sbase + (ck & (NSTAGE-1))*STAGE;
        uint32_t bb = ab + A_STAGE;
        const __half* ap = asrc + ck*32;
        cp16(ab + dA, ap);
        cp16(ab + dA + 64*AS_B, ap + (size_t)64*1152);
        int ij   = ck >> 2;              // 0..8
        int c0   = (ck & 3) << 5;        // 0,32,64,96
        int dip1 = ij / 3;
        int j3   = ij - dip1*3;
        const __half* bp = g_xs + ((size_t)j3*BB*CC + b*CC + c0)*SLAB
                         + (size_t)(r0 + dip1)*WW;
        cp16(bb + bdo[0], bp + bso[0]);
        cp16(bb + bdo[1], bp + bso[1]);
        cp16(bb + bdo[2], bp + bso[2]);
        if (bhas3) cp16(bb + bdo[3], bp + bso[3]);
        CP_COMMIT();
    };

    int lk  = lane & 15;
    int l16 = lane >> 4;

    auto compute_chunk = [&](int ck) {
        uint32_t ab = sbase + (ck & (NSTAGE-1))*STAGE;
        uint32_t bb = ab + A_STAGE;
        uint32_t hacc[4][7][2];
        uint32_t z = 0;
        #pragma unroll
        for (int ks = 0; ks < 2; ks++) {
            uint32_t afrag[4][4], bfrag[7][2];
            #pragma unroll
            for (int mt = 0; mt < 4; mt++) {
                int row = wm*64 + mt*16 + lk;
                uint32_t addr = ab + row*AS_B + l16*16 + ks*32;
                ldsm_x4(afrag[mt][0], afrag[mt][1], afrag[mt][2], afrag[mt][3], addr);
            }
            int rowk = ks*16 + lk;
            #pragma unroll
            for (int j = 0; j < 6; j += 2) {
                uint32_t addr = bb + rowk*BS_B + (wn*56 + (j + l16)*8)*2;
                ldsm_x4t(bfrag[j][0], bfrag[j][1], bfrag[j+1][0], bfrag[j+1][1], addr);
            }
            {
                uint32_t addr = bb + rowk*BS_B + (wn*56 + 48)*2;
                ldsm_x2t(bfrag[6][0], bfrag[6][1], addr);
            }
            if (ks == 0) {
                #pragma unroll
                for (int mt = 0; mt < 4; mt++)
                    #pragma unroll
                    for (int j = 0; j < 7; j++)
                        mma16816h_z(hacc[mt][j], afrag[mt], bfrag[j], z);
            } else {
                #pragma unroll
                for (int mt = 0; mt < 4; mt++)
                    #pragma unroll
                    for (int j = 0; j < 7; j++)
                        mma16816h(hacc[mt][j], afrag[mt], bfrag[j]);
            }
        }
        // promote chunk partial (fp16) into fp32 accumulators
        #pragma unroll
        for (int mt = 0; mt < 4; mt++)
            #pragma unroll
            for (int j = 0; j < 7; j++) {
                float2 lo = __half22float2(*(__half2*)&hacc[mt][j][0]);
                float2 hi = __half22float2(*(__half2*)&hacc[mt][j][1]);
                acc[mt][j][0] += lo.x; acc[mt][j][1] += lo.y;
                acc[mt][j][2] += hi.x; acc[mt][j][3] += hi.y;
            }
    };

    #pragma unroll
    for (int pk = 0; pk < PREF; pk++)
        issue_chunk(pk);

    for (int ck = 0; ck < NK; ck += 2) {
        CP_WAIT4();                       // chunks ck, ck+1 landed
        __syncthreads();
        if (ck + PREF     < NK) issue_chunk(ck + PREF);
        if (ck + PREF + 1 < NK) issue_chunk(ck + PREF + 1);
        compute_chunk(ck);
        compute_chunk(ck + 1);
    }
    CP_WAIT0();

    // epilogue: warp writes M64 x N56
    #pragma unroll
    for (int mt = 0; mt < 4; mt++) {
        int obase = bm*128 + wm*64 + mt*16 + (lane >> 2);
        #pragma unroll
        for (int half_ = 0; half_ < 2; half_++) {
            int o = obase + half_*8;
            float* dst = out + ((size_t)(b*OUTC + o))*HW + nt*224;
            #pragma unroll
            for (int j = 0; j < 7; j++) {
                int nb = wn*56 + j*8 + (lane & 3)*2;
                float2 v;
                v.x = acc[mt][j][half_*2 + 0];
                v.y = acc[mt][j][half_*2 + 1];
                *(float2*)(dst + nb) = v;
            }
        }
    }
}

// ---------------------------------------------------------------- launch
extern "C" void kernel_launch(void* const* d_in, const int* in_sizes, int n_in,
                              void* d_out, int out_size) {
    const float* x     = (const float*)d_in[0];
    const float* bank  = (const float*)d_in[1];
    const float* fc1_w = (const float*)d_in[2];
    const float* fc1_b = (const float*)d_in[3];
    const float* fc2_w = (const float*)d_in[4];
    const float* fc2_b = (const float*)d_in[5];
    float* out = (float*)d_out;

    cudaFuncSetAttribute(conv_mma_kernel,
                         cudaFuncAttributeMaxDynamicSharedMemorySize, SMEM_TOTAL);

    xprep_kernel<<<BB*CC, 256>>>(x);
    attn_kernel <<<BB, HIDN>>>(fc1_w, fc1_b, fc2_w, fc2_b);
    synth_kernel<<<(OUTC*1152)/256, 256>>>(bank);
    dim3 g(14, 2, BB);   // ntiles x mtiles x batch = 896
    conv_mma_kernel<<<g, 256, SMEM_TOTAL>>>(out);
}

// round 12
// speedup vs baseline: 1.1136x; 1.1136x over previous
#include <cuda_runtime.h>
#include <cuda_fp16.h>
#include <cstdint>

#define BB   32
#define CC   128
#define HH   56
#define WW   56
#define OUTC 256
#define KK   4
#define HIDN 64
#define HW   (HH*WW)

#define NKT     36              // K chunks per tile (1152 / 32)
#define NSTAGE  8
#define PREF    6
#define NSM     148
#define NTILES_TOTAL 896        // 32 b * 2 bm * 14 nt
#define SLABR   58
#define SLAB    (SLABR*WW)      // 3248 halves
#define AS_B    80              // A smem row stride bytes
#define BS_B    464             // B smem row stride bytes
#define A_STAGE (128*AS_B)      // 10240
#define B_STAGE (32*BS_B)       // 14848
#define STAGE   (A_STAGE + B_STAGE)     // 25088
#define SMEM_TOTAL (NSTAGE*STAGE)       // 200704

// scratch
__device__ float  g_pooled[BB*CC];
__device__ float  g_attn[BB*KK];
__device__ __half g_wh[(size_t)BB*OUTC*1152];      // [b][o][ij*128+c]
__device__ __half g_xs[(size_t)3*BB*CC*SLAB];      // [dj+1][b][c][58][56]

// ---------------------------------------------------------------- helpers
__device__ __forceinline__ uint32_t smem_u32(const void* p) {
    uint32_t a;
    asm("{ .reg .u64 t; cvta.to.shared.u64 t, %1; cvt.u32.u64 %0, t; }" : "=r"(a) : "l"(p));
    return a;
}
__device__ __forceinline__ void ldsm_x4(uint32_t& r0, uint32_t& r1, uint32_t& r2, uint32_t& r3,
                                        uint32_t addr) {
    asm volatile("ldmatrix.sync.aligned.m8n8.x4.shared.b16 {%0,%1,%2,%3}, [%4];"
                 : "=r"(r0), "=r"(r1), "=r"(r2), "=r"(r3) : "r"(addr));
}
__device__ __forceinline__ void ldsm_x4t(uint32_t& r0, uint32_t& r1, uint32_t& r2, uint32_t& r3,
                                         uint32_t addr) {
    asm volatile("ldmatrix.sync.aligned.m8n8.x4.trans.shared.b16 {%0,%1,%2,%3}, [%4];"
                 : "=r"(r0), "=r"(r1), "=r"(r2), "=r"(r3) : "r"(addr));
}
__device__ __forceinline__ void ldsm_x2t(uint32_t& r0, uint32_t& r1, uint32_t addr) {
    asm volatile("ldmatrix.sync.aligned.m8n8.x2.trans.shared.b16 {%0,%1}, [%2];"
                 : "=r"(r0), "=r"(r1) : "r"(addr));
}
__device__ __forceinline__ void mma16816(float* d, const uint32_t* a, const uint32_t* b) {
    asm volatile("mma.sync.aligned.m16n8k16.row.col.f32.f16.f16.f32 "
                 "{%0,%1,%2,%3}, {%4,%5,%6,%7}, {%8,%9}, {%0,%1,%2,%3};"
                 : "+f"(d[0]), "+f"(d[1]), "+f"(d[2]), "+f"(d[3])
                 : "r"(a[0]), "r"(a[1]), "r"(a[2]), "r"(a[3]), "r"(b[0]), "r"(b[1]));
}
__device__ __forceinline__ void cp16(uint32_t dst, const void* src) {
    asm volatile("cp.async.cg.shared.global [%0], [%1], 16;" :: "r"(dst), "l"(src));
}
#define CP_COMMIT() asm volatile("cp.async.commit_group;" ::: "memory")
#define CP_WAIT4()  asm volatile("cp.async.wait_group 4;" ::: "memory")
#define CP_WAIT0()  asm volatile("cp.async.wait_group 0;" ::: "memory")

// ---------------------------------------------------------------- x prep: fp16 shifts + pool
__global__ void xprep_kernel(const float* __restrict__ x) {
    int bc = blockIdx.x;
    const float* xp = x + (size_t)bc * HW;
    __half* d0 = g_xs + ((size_t)0*BB*CC + bc)*SLAB;
    __half* d1 = g_xs + ((size_t)1*BB*CC + bc)*SLAB;
    __half* d2 = g_xs + ((size_t)2*BB*CC + bc)*SLAB;
    int tid = threadIdx.x;
    if (tid < 56) {
        __half2 z = __floats2half2_rn(0.f, 0.f);
        *(__half2*)(d0 + tid*2) = z;  *(__half2*)(d0 + 57*WW + tid*2) = z;
        *(__half2*)(d1 + tid*2) = z;  *(__half2*)(d1 + 57*WW + tid*2) = z;
        *(__half2*)(d2 + tid*2) = z;  *(__half2*)(d2 + 57*WW + tid*2) = z;
    }
    float s = 0.f;
    #pragma unroll
    for (int it = 0; it < 7; it++) {
        int ip = tid + it*256;
        if (ip < HW/2) {
            int idx = ip*2;
            int w = idx % 56;
            float v0 = xp[idx], v1 = xp[idx+1];
            s += v0 + v1;
            float vm = (w > 0)  ? xp[idx-1] : 0.f;
            float vp = (w < 54) ? xp[idx+2] : 0.f;
            *(__half2*)(d0 + WW + idx) = __floats2half2_rn(vm, v0);
            *(__half2*)(d1 + WW + idx) = __floats2half2_rn(v0, v1);
            *(__half2*)(d2 + WW + idx) = __floats2half2_rn(v1, vp);
        }
    }
    #pragma unroll
    for (int o = 16; o; o >>= 1) s += __shfl_down_sync(0xffffffff, s, o);
    __shared__ float ws[8];
    int lane = tid & 31, wid = tid >> 5;
    if (lane == 0) ws[wid] = s;
    __syncthreads();
    if (tid == 0) {
        float t = 0.f;
        #pragma unroll
        for (int i = 0; i < 8; i++) t += ws[i];
        g_pooled[bc] = t * (1.0f / (float)HW);
    }
}

// ---------------------------------------------------------------- attn
__global__ void attn_kernel(const float* __restrict__ fc1_w, const float* __restrict__ fc1_b,
                            const float* __restrict__ fc2_w, const float* __restrict__ fc2_b) {
    int b = blockIdx.x;
    __shared__ float sp[CC];
    __shared__ float hdn[HIDN];
    int t = threadIdx.x;
    for (int i = t; i < CC; i += HIDN) sp[i] = g_pooled[b*CC + i];
    __syncthreads();
    float a = fc1_b[t];
    #pragma unroll 8
    for (int c = 0; c < CC; c++) a += sp[c] * fc1_w[t*CC + c];
    hdn[t] = fmaxf(a, 0.f);
    __syncthreads();
    if (t == 0) {
        float lg[KK];
        float mx = -1e30f;
        #pragma unroll
        for (int k = 0; k < KK; k++) {
            float s = fc2_b[k];
            for (int h = 0; h < HIDN; h++) s += hdn[h] * fc2_w[k*HIDN + h];
            lg[k] = s; mx = fmaxf(mx, s);
        }
        float den = 0.f;
        #pragma unroll
        for (int k = 0; k < KK; k++) { lg[k] = expf(lg[k] - mx); den += lg[k]; }
        float inv = 1.0f / den;
        #pragma unroll
        for (int k = 0; k < KK; k++) g_attn[b*KK + k] = lg[k] * inv;
    }
}

// ---------------------------------------------------------------- weight synthesis (fp16 out)
__global__ void synth_kernel(const float* __restrict__ bank) {
    __shared__ float sat[BB*KK];
    if (threadIdx.x < BB*KK) sat[threadIdx.x] = g_attn[threadIdx.x];
    __syncthreads();
    int idx = blockIdx.x * blockDim.x + threadIdx.x;
    int c   = idx & 127;
    int oij = idx >> 7;
    int ij  = oij % 9;
    int o   = oij / 9;
    float bv[KK];
    #pragma unroll
    for (int k = 0; k < KK; k++)
        bv[k] = __ldg(&bank[((size_t)k*OUTC + o) * 1152 + c*9 + ij]);
    size_t dst = (size_t)o*1152 + ij*128 + c;
    #pragma unroll 4
    for (int b = 0; b < BB; b++) {
        float w = 0.f;
        #pragma unroll
        for (int k = 0; k < KK; k++) w += sat[b*KK + k] * bv[k];
        g_wh[(size_t)b * (OUTC*1152) + dst] = __float2half_rn(w);
    }
}

// ---------------------------------------------------------------- persistent fp16 mma.sync conv
// 148 persistent CTAs; each processes 6-7 tiles (tile = b, bm(128 o), nt(224 pos)).
// Continuous global chunk stream through an 8-stage cp.async ring.
__global__ void __launch_bounds__(256, 1)
conv_mma_kernel(float* __restrict__ out) {
    extern __shared__ __align__(16) char smem[];

    int tid  = threadIdx.x;
    int wid  = tid >> 5;
    int lane = tid & 31;
    int wm   = wid >> 2;          // 0..1 -> m base wm*64
    int wn   = wid & 3;           // 0..3 -> n base wn*56
    int cta  = blockIdx.x;        // 0..147

    uint32_t sbase = smem_u32(smem);

    int ntiles = (cta < NTILES_TOTAL - 6*NSM) ? 7 : 6;
    int NCH = ntiles * NKT;

    // ---- per-thread loader geometry (tile-invariant) ----
    int ar = tid >> 2, aq = tid & 3;
    uint32_t dA = (uint32_t)ar*AS_B + aq*16;
    size_t   aoff = (size_t)ar*1152 + aq*8;
    size_t   bso[4];
    uint32_t bdo[4];
    #pragma unroll
    for (int it = 0; it < 4; it++) {
        int idx = tid + it*256;
        int c   = idx / 28, q = idx - c*28;
        bso[it] = (size_t)c*SLAB + q*8;
        bdo[it] = (uint32_t)c*BS_B + q*16;
    }
    bool bhas3 = tid < 128;

    // ---- issue cursor ----
    const __half* a_t;            // A base for issue tile (thread-offset applied)
    const __half* bx_t;           // B base for issue tile (includes r0*WW)
    int iord = 0, ick = 0;
    auto set_issue_tile = [&](int ord) {
        int id  = cta + NSM*ord;
        int nt  = id % 14;
        int rem = id / 14;
        int bmq = rem & 1;
        int bq  = rem >> 1;
        a_t  = g_wh + ((size_t)bq*OUTC + bmq*128)*1152 + aoff;
        bx_t = g_xs + (size_t)bq*CC*SLAB + (size_t)(nt*4)*WW;
    };
    set_issue_tile(0);

    auto issue_next = [&](int g) {
        uint32_t ab = sbase + (g & (NSTAGE-1))*STAGE;
        uint32_t bb = ab + A_STAGE;
        const __half* ap = a_t + ick*32;
        cp16(ab + dA, ap);
        cp16(ab + dA + 64*AS_B, ap + (size_t)64*1152);
        int ij   = ick >> 2;
        int c0   = (ick & 3) << 5;
        int dip1 = ij / 3;
        int j3   = ij - dip1*3;
        const __half* bp = bx_t + ((size_t)j3*BB*CC + c0)*SLAB + (size_t)dip1*WW;
        cp16(bb + bdo[0], bp + bso[0]);
        cp16(bb + bdo[1], bp + bso[1]);
        cp16(bb + bdo[2], bp + bso[2]);
        if (bhas3) cp16(bb + bdo[3], bp + bso[3]);
        CP_COMMIT();
        if (++ick == NKT) {
            ick = 0;
            if (++iord < ntiles) set_issue_tile(iord);
        }
    };

    // ---- compute cursor ----
    int ce_b, ce_bm, ce_nt;
    int cord = 0;
    auto set_comp_tile = [&](int ord) {
        int id  = cta + NSM*ord;
        ce_nt   = id % 14;
        int rem = id / 14;
        ce_bm   = rem & 1;
        ce_b    = rem >> 1;
    };
    set_comp_tile(0);

    float acc[4][7][4];
    #pragma unroll
    for (int i = 0; i < 4; i++)
        #pragma unroll
        for (int j = 0; j < 7; j++)
            #pragma unroll
            for (int q = 0; q < 4; q++) acc[i][j][q] = 0.f;

    int lk  = lane & 15;
    int l16 = lane >> 4;

    auto compute_chunk = [&](int g) {
        uint32_t ab = sbase + (g & (NSTAGE-1))*STAGE;
        uint32_t bb = ab + A_STAGE;
        #pragma unroll
        for (int ks = 0; ks < 2; ks++) {
            uint32_t afrag[4][4], bfrag[7][2];
            #pragma unroll
            for (int mt = 0; mt < 4; mt++) {
                int row = wm*64 + mt*16 + lk;
                uint32_t addr = ab + row*AS_B + l16*16 + ks*32;
                ldsm_x4(afrag[mt][0], afrag[mt][1], afrag[mt][2], afrag[mt][3], addr);
            }
            int rowk = ks*16 + lk;
            #pragma unroll
            for (int j = 0; j < 6; j += 2) {
                uint32_t addr = bb + rowk*BS_B + (wn*56 + (j + l16)*8)*2;
                ldsm_x4t(bfrag[j][0], bfrag[j][1], bfrag[j+1][0], bfrag[j+1][1], addr);
            }
            {
                uint32_t addr = bb + rowk*BS_B + (wn*56 + 48)*2;
                ldsm_x2t(bfrag[6][0], bfrag[6][1], addr);
            }
            #pragma unroll
            for (int mt = 0; mt < 4; mt++)
                #pragma unroll
                for (int j = 0; j < 7; j++)
                    mma16816(acc[mt][j], afrag[mt], bfrag[j]);
        }
    };

    // ---- prologue ----
    #pragma unroll
    for (int k = 0; k < PREF; k++)
        issue_next(k);

    int cck = 0;
    for (int g = 0; g < NCH; g += 2) {
        CP_WAIT4();                       // chunks g, g+1 landed
        __syncthreads();
        if (g + PREF     < NCH) issue_next(g + PREF);
        if (g + PREF + 1 < NCH) issue_next(g + PREF + 1);
        compute_chunk(g);
        compute_chunk(g + 1);
        cck += 2;
        if (cck == NKT) {
            // epilogue for finished tile; overlaps with in-flight prefetch
            #pragma unroll
            for (int mt = 0; mt < 4; mt++) {
                int obase = ce_bm*128 + wm*64 + mt*16 + (lane >> 2);
                #pragma unroll
                for (int half_ = 0; half_ < 2; half_++) {
                    int o = obase + half_*8;
                    float* dst = out + ((size_t)(ce_b*OUTC + o))*HW + ce_nt*224;
                    #pragma unroll
                    for (int j = 0; j < 7; j++) {
                        int nb = wn*56 + j*8 + (lane & 3)*2;
                        float2 v;
                        v.x = acc[mt][j][half_*2 + 0];
                        v.y = acc[mt][j][half_*2 + 1];
                        *(float2*)(dst + nb) = v;
                    }
                }
            }
            cck = 0;
            if (++cord < ntiles) {
                set_comp_tile(cord);
                #pragma unroll
                for (int i = 0; i < 4; i++)
                    #pragma unroll
                    for (int j = 0; j < 7; j++)
                        #pragma unroll
                        for (int q = 0; q < 4; q++) acc[i][j][q] = 0.f;
            }
        }
    }
    CP_WAIT0();
}

// ---------------------------------------------------------------- launch
extern "C" void kernel_launch(void* const* d_in, const int* in_sizes, int n_in,
                              void* d_out, int out_size) {
    const float* x     = (const float*)d_in[0];
    const float* bank  = (const float*)d_in[1];
    const float* fc1_w = (const float*)d_in[2];
    const float* fc1_b = (const float*)d_in[3];
    const float* fc2_w = (const float*)d_in[4];
    const float* fc2_b = (const float*)d_in[5];
    float* out = (float*)d_out;

    cudaFuncSetAttribute(conv_mma_kernel,
                         cudaFuncAttributeMaxDynamicSharedMemorySize, SMEM_TOTAL);

    xprep_kernel<<<BB*CC, 256>>>(x);
    attn_kernel <<<BB, HIDN>>>(fc1_w, fc1_b, fc2_w, fc2_b);
    synth_kernel<<<(OUTC*1152)/256, 256>>>(bank);
    conv_mma_kernel<<<NSM, 256, SMEM_TOTAL>>>(out);
}

// round 13
// speedup vs baseline: 1.2335x; 1.1077x over previous
#include <cuda_runtime.h>
#include <cuda_fp16.h>
#include <cstdint>

#define BB   32
#define CC   128
#define HH   56
#define WW   56
#define OUTC 256
#define KK   4
#define HIDN 64
#define HW   (HH*WW)

#define NK      36              // K chunks (1152 / 32)
#define NSTAGE  8
#define PREF    6
#define SLABR   58
#define SLAB    (SLABR*WW)      // 3248 halves
#define AS_B    80              // A smem row stride bytes
#define BS_B    464             // B smem row stride bytes
#define A_STAGE (128*AS_B)      // 10240
#define B_STAGE (32*BS_B)       // 14848
#define STAGE   (A_STAGE + B_STAGE)     // 25088
#define SMEM_TOTAL (NSTAGE*STAGE)       // 200704

// scratch
__device__ float  g_pooled[BB*CC];
__device__ float  g_attn[BB*KK];
__device__ __half g_wh[(size_t)BB*OUTC*1152];      // [b][o][ij*128+c]
__device__ __half g_xs[(size_t)3*BB*CC*SLAB];      // [dj+1][b][c][58][56]

// ---------------------------------------------------------------- helpers
__device__ __forceinline__ uint32_t smem_u32(const void* p) {
    uint32_t a;
    asm("{ .reg .u64 t; cvta.to.shared.u64 t, %1; cvt.u32.u64 %0, t; }" : "=r"(a) : "l"(p));
    return a;
}
__device__ __forceinline__ void ldsm_x4(uint32_t& r0, uint32_t& r1, uint32_t& r2, uint32_t& r3,
                                        uint32_t addr) {
    asm volatile("ldmatrix.sync.aligned.m8n8.x4.shared.b16 {%0,%1,%2,%3}, [%4];"
                 : "=r"(r0), "=r"(r1), "=r"(r2), "=r"(r3) : "r"(addr));
}
__device__ __forceinline__ void ldsm_x2t(uint32_t& r0, uint32_t& r1, uint32_t addr) {
    asm volatile("ldmatrix.sync.aligned.m8n8.x2.trans.shared.b16 {%0,%1}, [%2];"
                 : "=r"(r0), "=r"(r1) : "r"(addr));
}
__device__ __forceinline__ void mma16816(float* d, const uint32_t* a, const uint32_t* b) {
    asm volatile("mma.sync.aligned.m16n8k16.row.col.f32.f16.f16.f32 "
                 "{%0,%1,%2,%3}, {%4,%5,%6,%7}, {%8,%9}, {%0,%1,%2,%3};"
                 : "+f"(d[0]), "+f"(d[1]), "+f"(d[2]), "+f"(d[3])
                 : "r"(a[0]), "r"(a[1]), "r"(a[2]), "r"(a[3]), "r"(b[0]), "r"(b[1]));
}
__device__ __forceinline__ void cp16(uint32_t dst, const void* src) {
    asm volatile("cp.async.cg.shared.global [%0], [%1], 16;" :: "r"(dst), "l"(src));
}
#define CP_COMMIT() asm volatile("cp.async.commit_group;" ::: "memory")
#define CP_WAIT4()  asm volatile("cp.async.wait_group 4;" ::: "memory")
#define CP_WAIT0()  asm volatile("cp.async.wait_group 0;" ::: "memory")

// ---------------------------------------------------------------- x prep: smem-staged fp16 shifts + pool
// One block per (b,c). x read once via float4; shifts computed from smem.
__global__ void xprep_kernel(const float* __restrict__ x) {
    __shared__ float sx[HW];                 // 12.5 KB
    int bc = blockIdx.x;
    const float4* xp4 = (const float4*)(x + (size_t)bc * HW);
    __half* d0 = g_xs + ((size_t)0*BB*CC + bc)*SLAB;
    __half* d1 = g_xs + ((size_t)1*BB*CC + bc)*SLAB;
    __half* d2 = g_xs + ((size_t)2*BB*CC + bc)*SLAB;
    int tid = threadIdx.x;

    float s = 0.f;
    #pragma unroll
    for (int it = 0; it < 4; it++) {
        int i = tid + it*256;
        if (i < HW/4) {
            float4 v = xp4[i];
            ((float4*)sx)[i] = v;
            s += v.x + v.y + v.z + v.w;
        }
    }
    // zero pad rows (rows 0 and 57 of each slab)
    if (tid < 56) {
        __half2 z = __floats2half2_rn(0.f, 0.f);
        *(__half2*)(d0 + tid*2) = z;  *(__half2*)(d0 + 57*WW + tid*2) = z;
        *(__half2*)(d1 + tid*2) = z;  *(__half2*)(d1 + 57*WW + tid*2) = z;
        *(__half2*)(d2 + tid*2) = z;  *(__half2*)(d2 + 57*WW + tid*2) = z;
    }
    __syncthreads();

    #pragma unroll
    for (int it = 0; it < 7; it++) {
        int ip = tid + it*256;               // pair index
        if (ip < HW/2) {
            int idx = ip*2;
            int w = idx % 56;
            float v0 = sx[idx], v1 = sx[idx+1];
            float vm = (w > 0)  ? sx[idx-1] : 0.f;
            float vp = (w < 54) ? sx[idx+2] : 0.f;
            *(__half2*)(d0 + WW + idx) = __floats2half2_rn(vm, v0);
            *(__half2*)(d1 + WW + idx) = __floats2half2_rn(v0, v1);
            *(__half2*)(d2 + WW + idx) = __floats2half2_rn(v1, vp);
        }
    }

    #pragma unroll
    for (int o = 16; o; o >>= 1) s += __shfl_down_sync(0xffffffff, s, o);
    __shared__ float ws[8];
    int lane = tid & 31, wid = tid >> 5;
    if (lane == 0) ws[wid] = s;
    __syncthreads();
    if (tid == 0) {
        float t = 0.f;
        #pragma unroll
        for (int i = 0; i < 8; i++) t += ws[i];
        g_pooled[bc] = t * (1.0f / (float)HW);
    }
}

// ---------------------------------------------------------------- attn
__global__ void attn_kernel(const float* __restrict__ fc1_w, const float* __restrict__ fc1_b,
                            const float* __restrict__ fc2_w, const float* __restrict__ fc2_b) {
    int b = blockIdx.x;
    __shared__ float sp[CC];
    __shared__ float hdn[HIDN];
    int t = threadIdx.x;
    for (int i = t; i < CC; i += HIDN) sp[i] = g_pooled[b*CC + i];
    __syncthreads();
    float a = fc1_b[t];
    #pragma unroll 8
    for (int c = 0; c < CC; c++) a += sp[c] * fc1_w[t*CC + c];
    hdn[t] = fmaxf(a, 0.f);
    __syncthreads();
    if (t == 0) {
        float lg[KK];
        float mx = -1e30f;
        #pragma unroll
        for (int k = 0; k < KK; k++) {
            float s = fc2_b[k];
            for (int h = 0; h < HIDN; h++) s += hdn[h] * fc2_w[k*HIDN + h];
            lg[k] = s; mx = fmaxf(mx, s);
        }
        float den = 0.f;
        #pragma unroll
        for (int k = 0; k < KK; k++) { lg[k] = expf(lg[k] - mx); den += lg[k]; }
        float inv = 1.0f / den;
        #pragma unroll
        for (int k = 0; k < KK; k++) g_attn[b*KK + k] = lg[k] * inv;
    }
}

// ---------------------------------------------------------------- weight synthesis (fp16, coalesced reads)
// thread <-> (o, c). Reads bank[k][o][c*9..c*9+9) contiguous; writes all 9 ij x 32 b.
__global__ void synth_kernel(const float* __restrict__ bank) {
    __shared__ float sat[BB*KK];
    if (threadIdx.x < BB*KK) sat[threadIdx.x] = g_attn[threadIdx.x];
    __syncthreads();
    int idx = blockIdx.x * blockDim.x + threadIdx.x;   // < OUTC*CC = 32768
    int c   = idx & 127;
    int o   = idx >> 7;
    float bv[KK][9];
    #pragma unroll
    for (int k = 0; k < KK; k++) {
        const float* src = bank + ((size_t)k*OUTC + o)*1152 + c*9;
        #pragma unroll
        for (int ij = 0; ij < 9; ij++) bv[k][ij] = __ldg(src + ij);
    }
    __half* dst = g_wh + (size_t)o*1152 + c;
    #pragma unroll 4
    for (int b = 0; b < BB; b++) {
        float a0 = sat[b*KK+0], a1 = sat[b*KK+1], a2 = sat[b*KK+2], a3 = sat[b*KK+3];
        __half* db = dst + (size_t)b*(OUTC*1152);
        #pragma unroll
        for (int ij = 0; ij < 9; ij++) {
            float w = a0*bv[0][ij] + a1*bv[1][ij] + a2*bv[2][ij] + a3*bv[3][ij];
            db[ij*128] = __float2half_rn(w);
        }
    }
}

// ---------------------------------------------------------------- fp16 mma.sync conv (R9 config)
// CTA: b=z, bm=y (128 o), nt=x (224 pos = 4 rows). 8 warps (2m x 4n), warp M64xN56.
// K=32 chunks, 8-stage cp.async ring, prefetch 6, one barrier per 2 chunks.
__global__ void __launch_bounds__(256, 1)
conv_mma_kernel(float* __restrict__ out) {
    extern __shared__ __align__(16) char smem[];

    int tid  = threadIdx.x;
    int wid  = tid >> 5;
    int lane = tid & 31;
    int wm   = wid >> 2;          // 0..1 -> m base wm*64
    int wn   = wid & 3;           // 0..3 -> n base wn*56
    int b    = blockIdx.z;
    int bm   = blockIdx.y;
    int nt   = blockIdx.x;        // 0..13
    int r0   = nt * 4;

    uint32_t sbase = smem_u32(smem);

    const __half* wg = g_wh + ((size_t)b * OUTC + bm*128) * 1152;

    float acc[4][7][4];
    #pragma unroll
    for (int i = 0; i < 4; i++)
        #pragma unroll
        for (int j = 0; j < 7; j++)
            #pragma unroll
            for (int q = 0; q < 4; q++) acc[i][j][q] = 0.f;

    // ---- A loader: 2 cp16/thread. row = tid>>2 (+64), q = tid&3.
    int ar = tid >> 2, aq = tid & 3;
    const __half* asrc = wg + (size_t)ar*1152 + aq*8;    // + ck*32 per chunk
    uint32_t dA = (uint32_t)ar*AS_B + aq*16;
    // ---- B loader: 3.5 cp16/thread. idx = tid + it*256; c = idx/28, q = idx%28.
    size_t   bso[4];
    uint32_t bdo[4];
    #pragma unroll
    for (int it = 0; it < 4; it++) {
        int idx = tid + it*256;
        int c   = idx / 28, q = idx - c*28;
        bso[it] = (size_t)c*SLAB + q*8;
        bdo[it] = (uint32_t)c*BS_B + q*16;
    }
    bool bhas3 = tid < 128;

    auto issue_chunk = [&](int ck) {
        uint32_t ab = sbase + (ck & (NSTAGE-1))*STAGE;
        uint32_t bb = ab + A_STAGE;
        const __half* ap = asrc + ck*32;
        cp16(ab + dA, ap);
        cp16(ab + dA + 64*AS_B, ap + (size_t)64*1152);
        int ij   = ck >> 2;              // 0..8
        int c0   = (ck & 3) << 5;        // 0,32,64,96
        int dip1 = ij / 3;
        int j3   = ij - dip1*3;
        const __half* bp = g_xs + ((size_t)j3*BB*CC + b*CC + c0)*SLAB
                         + (size_t)(r0 + dip1)*WW;
        cp16(bb + bdo[0], bp + bso[0]);
        cp16(bb + bdo[1], bp + bso[1]);
        cp16(bb + bdo[2], bp + bso[2]);
        if (bhas3) cp16(bb + bdo[3], bp + bso[3]);
        CP_COMMIT();
    };

    int lk  = lane & 15;
    int l16 = lane >> 4;

    auto compute_chunk = [&](int ck) {
        uint32_t ab = sbase + (ck & (NSTAGE-1))*STAGE;
        uint32_t bb = ab + A_STAGE;
        #pragma unroll
        for (int ks = 0; ks < 2; ks++) {
            uint32_t afrag[4][4], bfrag[7][2];
            #pragma unroll
            for (int mt = 0; mt < 4; mt++) {
                int row = wm*64 + mt*16 + lk;
                uint32_t addr = ab + row*AS_B + l16*16 + ks*32;
                ldsm_x4(afrag[mt][0], afrag[mt][1], afrag[mt][2], afrag[mt][3], addr);
            }
            int rowk = ks*16 + lk;
            #pragma unroll
            for (int j = 0; j < 7; j++) {
                uint32_t addr = bb + rowk*BS_B + (wn*56 + j*8)*2;
                ldsm_x2t(bfrag[j][0], bfrag[j][1], addr);
            }
            #pragma unroll
            for (int mt = 0; mt < 4; mt++)
                #pragma unroll
                for (int j = 0; j < 7; j++)
                    mma16816(acc[mt][j], afrag[mt], bfrag[j]);
        }
    };

    #pragma unroll
    for (int pk = 0; pk < PREF; pk++)
        issue_chunk(pk);

    for (int ck = 0; ck < NK; ck += 2) {
        CP_WAIT4();                       // chunks ck, ck+1 landed
        __syncthreads();
        if (ck + PREF     < NK) issue_chunk(ck + PREF);
        if (ck + PREF + 1 < NK) issue_chunk(ck + PREF + 1);
        compute_chunk(ck);
        compute_chunk(ck + 1);
    }
    CP_WAIT0();

    // epilogue: warp writes M64 x N56
    #pragma unroll
    for (int mt = 0; mt < 4; mt++) {
        int obase = bm*128 + wm*64 + mt*16 + (lane >> 2);
        #pragma unroll
        for (int half_ = 0; half_ < 2; half_++) {
            int o = obase + half_*8;
            float* dst = out + ((size_t)(b*OUTC + o))*HW + nt*224;
            #pragma unroll
            for (int j = 0; j < 7; j++) {
                int nb = wn*56 + j*8 + (lane & 3)*2;
                float2 v;
                v.x = acc[mt][j][half_*2 + 0];
                v.y = acc[mt][j][half_*2 + 1];
                *(float2*)(dst + nb) = v;
            }
        }
    }
}

// ---------------------------------------------------------------- launch
extern "C" void kernel_launch(void* const* d_in, const int* in_sizes, int n_in,
                              void* d_out, int out_size) {
    const float* x     = (const float*)d_in[0];
    const float* bank  = (const float*)d_in[1];
    const float* fc1_w = (const float*)d_in[2];
    const float* fc1_b = (const float*)d_in[3];
    const float* fc2_w = (const float*)d_in[4];
    const float* fc2_b = (const float*)d_in[5];
    float* out = (float*)d_out;

    cudaFuncSetAttribute(conv_mma_kernel,
                         cudaFuncAttributeMaxDynamicSharedMemorySize, SMEM_TOTAL);

    xprep_kernel<<<BB*CC, 256>>>(x);
    attn_kernel <<<BB, HIDN>>>(fc1_w, fc1_b, fc2_w, fc2_b);
    synth_kernel<<<(OUTC*CC)/256, 256>>>(bank);
    dim3 g(14, 2, BB);   // ntiles x mtiles x batch = 896
    conv_mma_kernel<<<g, 256, SMEM_TOTAL>>>(out);
}